// round 4
// baseline (speedup 1.0000x reference)
#include <cuda_runtime.h>

// SSGP folded: f[n,i] = sum_{b<1024} cos(sim[n,b] + phi_b) * gmat[b,i]
// sim = x . q^T, q = eps/lam. Two N=8192 x B=1024 x K=64 GEMMs via f32x2 FFMA2.
// No basis-split: each block owns 32 output rows and walks all 16 chunks.

#define PADB 68   // stride for 64-wide b/j tables
#define PADN 36   // stride for 32-wide n tiles

__device__ float g_qT[64 * 1024];    // [j][b]
__device__ float g_mat[1024 * 64];   // [b][i] with R folded in
__device__ float g_phi[1024];
__device__ float g_R[1024];

// ---------- prep ----------
__global__ void ssgp_prep1(const float* __restrict__ w) {
    int b = blockIdx.x * blockDim.x + threadIdx.x;   // 1024 threads
    float S = w[b] + w[b + 1024];
    float C = w[2048 + b] - w[3072 + b];
    g_R[b] = sqrtf(S * S + C * C);
    g_phi[b] = atan2f(S, C);
}

__global__ void ssgp_prep2(const float* __restrict__ eps,
                           const float* __restrict__ lam,
                           const float* __restrict__ eta) {
    int idx = blockIdx.x * blockDim.x + threadIdx.x; // 65536 threads
    int b = idx >> 6, i = idx & 63;
    float e2 = eta[0] * eta[0];
    float R = g_R[b];
    float q = eps[b * 64 + i] / lam[i];
    g_qT[i * 1024 + b] = q;
    float m;
    if (i < 32) m = R * (eps[b * 64 + i + 32] / lam[i + 32]);
    else        m = -R * (eps[b * 64 + i - 32] / lam[i - 32] + e2 * q);
    g_mat[b * 64 + i] = m;
}

// ---------- f32x2 helpers ----------
typedef unsigned long long u64;
__device__ __forceinline__ u64 pack2(float lo, float hi) {
    u64 d; asm("mov.b64 %0, {%1, %2};" : "=l"(d) : "f"(lo), "f"(hi)); return d;
}
__device__ __forceinline__ u64 splat2(float s) {
    u64 d; asm("mov.b64 %0, {%1, %1};" : "=l"(d) : "f"(s)); return d;
}
__device__ __forceinline__ float2 unpack2(u64 v) {
    float lo, hi; asm("mov.b64 {%0, %1}, %2;" : "=f"(lo), "=f"(hi) : "l"(v));
    return make_float2(lo, hi);
}
#define FMA2(acc, a, b) \
    asm("fma.rn.f32x2 %0, %1, %2, %0;" : "+l"(acc) : "l"(a), "l"(b))

__device__ __forceinline__ void cpa16(float* dst, const float* src) {
    unsigned d = (unsigned)__cvta_generic_to_shared(dst);
    asm volatile("cp.async.cg.shared.global [%0], [%1], 16;" :: "r"(d), "l"(src));
}

// q chunk: 64x64 floats, 128 threads -> 8 cp.async each
__device__ __forceinline__ void prefetch_q(int c, float* sq, float* sp, int tid) {
    if (c < 16) {
#pragma unroll
        for (int r = 0; r < 8; r++) {
            int e = tid + r * 128;
            int k = e >> 4, v = (e & 15) << 2;
            cpa16(&sq[k * PADB + v], &g_qT[k * 1024 + c * 64 + v]);
        }
        if (tid < 16) cpa16(&sp[tid * 4], &g_phi[c * 64 + tid * 4]);
    }
    asm volatile("cp.async.commit_group;");
}

__device__ __forceinline__ void prefetch_g(int c, float* sg, int tid) {
    if (c < 16) {
#pragma unroll
        for (int r = 0; r < 8; r++) {
            int e = tid + r * 128;
            int b = e >> 4, v = (e & 15) << 2;
            cpa16(&sg[b * PADB + v], &g_mat[(c * 64 + b) * 64 + v]);
        }
    }
    asm volatile("cp.async.commit_group;");
}

// ---------- main ----------
__global__ void __launch_bounds__(128)
ssgp_main(const float* __restrict__ x, float* __restrict__ out) {
    extern __shared__ float smem[];
    float* sx  = smem;                  // x tile transposed [j][n]  64 x PADN
    float* sq  = sx  + 64 * PADN;       // q chunk           [j][b]  64 x PADB
    float* sg0 = sq  + 64 * PADB;       // mat chunk buf0    [b][i]
    float* sg1 = sg0 + 64 * PADB;
    float* sc  = sg1 + 64 * PADB;       // coeff transposed  [b][n]  64 x PADN
    float* sp  = sc  + 64 * PADN;       // phi chunk [64]

    const int tid  = threadIdx.x;
    const int row0 = blockIdx.x * 32;

    // pipeline prologue: q0+p0 | g0 | g1
    prefetch_q(0, sq, sp, tid);
    prefetch_g(0, sg0, tid);
    prefetch_g(1, sg1, tid);

    // load x tile transposed to [j][n] (32 rows x 64 cols)
#pragma unroll
    for (int r = 0; r < 4; r++) {
        int e = tid + r * 128;
        int n = e >> 4, jv = (e & 15) << 2;
        float4 v = *(const float4*)&x[(row0 + n) * 64 + jv];
        sx[(jv + 0) * PADN + n] = v.x;
        sx[(jv + 1) * PADN + n] = v.y;
        sx[(jv + 2) * PADN + n] = v.z;
        sx[(jv + 3) * PADN + n] = v.w;
    }

    const int tx = tid & 15, ty = tid >> 4;   // tx: 16, ty: 8
    const int n0 = ty * 4, b0 = tx * 4;

    u64 facc[2][4];
#pragma unroll
    for (int p = 0; p < 2; p++)
#pragma unroll
        for (int i = 0; i < 4; i++) facc[p][i] = 0ULL;

    for (int c = 0; c < 16; ++c) {
        // in flight: {q_c (from prev iter)}, {g_{c+1}} -> allow newest 1 pending
        asm volatile("cp.async.wait_group 1;" ::: "memory");
        __syncthreads();
        const float* sg = (c & 1) ? sg1 : sg0;

        // GEMM1: sim = x_tile . q_chunk^T (pairs packed along n)
        u64 simp[2][4];
#pragma unroll
        for (int p = 0; p < 2; p++)
#pragma unroll
            for (int j = 0; j < 4; j++) simp[p][j] = 0ULL;

#pragma unroll 16
        for (int k = 0; k < 64; k++) {
            float4 xv = *(const float4*)&sx[k * PADN + n0];
            float4 sv = *(const float4*)&sq[k * PADB + b0];
            u64 x01 = pack2(xv.x, xv.y), x23 = pack2(xv.z, xv.w);
            u64 q0 = splat2(sv.x), q1 = splat2(sv.y);
            u64 q2 = splat2(sv.z), q3 = splat2(sv.w);
            FMA2(simp[0][0], x01, q0); FMA2(simp[0][1], x01, q1);
            FMA2(simp[0][2], x01, q2); FMA2(simp[0][3], x01, q3);
            FMA2(simp[1][0], x23, q0); FMA2(simp[1][1], x23, q1);
            FMA2(simp[1][2], x23, q2); FMA2(simp[1][3], x23, q3);
        }

        // coeff = cos(sim + phi) -> sc[b][n]
        float ph[4] = {sp[b0], sp[b0 + 1], sp[b0 + 2], sp[b0 + 3]};
#pragma unroll
        for (int jj = 0; jj < 4; jj++) {
            float2 a = unpack2(simp[0][jj]);
            float2 b = unpack2(simp[1][jj]);
            float4 cv = make_float4(__cosf(a.x + ph[jj]), __cosf(a.y + ph[jj]),
                                    __cosf(b.x + ph[jj]), __cosf(b.y + ph[jj]));
            *(float4*)&sc[(b0 + jj) * PADN + n0] = cv;
        }
        __syncthreads();               // sc ready; sq/sp fully consumed
        prefetch_q(c + 1, sq, sp, tid);     // overlaps GEMM2

        // GEMM2: facc += coeff . mat_chunk
#pragma unroll 16
        for (int b = 0; b < 64; b++) {
            float4 cv = *(const float4*)&sc[b * PADN + n0];
            float4 gv = *(const float4*)&sg[b * PADB + b0];
            u64 c01 = pack2(cv.x, cv.y), c23 = pack2(cv.z, cv.w);
            u64 g0 = splat2(gv.x), g1 = splat2(gv.y);
            u64 g2 = splat2(gv.z), g3 = splat2(gv.w);
            FMA2(facc[0][0], c01, g0); FMA2(facc[0][1], c01, g1);
            FMA2(facc[0][2], c01, g2); FMA2(facc[0][3], c01, g3);
            FMA2(facc[1][0], c23, g0); FMA2(facc[1][1], c23, g1);
            FMA2(facc[1][2], c23, g2); FMA2(facc[1][3], c23, g3);
        }
        __syncthreads();               // sg[c&1] and sc fully consumed
        prefetch_g(c + 2, (c & 1) ? sg1 : sg0, tid);   // refill freed buffer
    }

#pragma unroll
    for (int p = 0; p < 2; p++) {
        float2 v0 = unpack2(facc[p][0]);
        float2 v1 = unpack2(facc[p][1]);
        float2 v2 = unpack2(facc[p][2]);
        float2 v3 = unpack2(facc[p][3]);
        float4 lo = make_float4(v0.x, v1.x, v2.x, v3.x);
        float4 hi = make_float4(v0.y, v1.y, v2.y, v3.y);
        *(float4*)&out[(row0 + n0 + 2 * p) * 64 + b0]     = lo;
        *(float4*)&out[(row0 + n0 + 2 * p + 1) * 64 + b0] = hi;
    }
}

extern "C" void kernel_launch(void* const* d_in, const int* in_sizes, int n_in,
                              void* d_out, int out_size) {
    // inputs: 0=t(1), 1=x(8192*64), 2=epsilon(2048*64), 3=lam(64), 4=eta(1), 5=w(4096)
    const float* x   = (const float*)d_in[1];
    const float* eps = (const float*)d_in[2];
    const float* lam = (const float*)d_in[3];
    const float* eta = (const float*)d_in[4];
    const float* w   = (const float*)d_in[5];
    float* out = (float*)d_out;

    ssgp_prep1<<<4, 256>>>(w);
    ssgp_prep2<<<256, 256>>>(eps, lam, eta);

    size_t smem = (size_t)(2 * 64 * PADN + 3 * 64 * PADB + 64) * sizeof(float);
    cudaFuncSetAttribute(ssgp_main, cudaFuncAttributeMaxDynamicSharedMemorySize,
                         (int)smem);
    ssgp_main<<<256, 128, smem>>>(x, out);
}

// round 8
// speedup vs baseline: 2.3867x; 2.3867x over previous
#include <cuda_runtime.h>
#include <cuda_bf16.h>
#include <cstdint>

// ============================================================================
// SSGP folded: f[n,i] = sum_{b<1024} cos(sim[n,b]+phi_b) * mat[b,i]
// via classic mma.sync.m16n8k16 bf16 (base ISA, works under compute_103).
// Split precision: x=xh+xl, q=qh+ql: sim = xh qh + xl qh + xh ql (drop lo*lo)
//                  c=ch+cl, m=mh+ml: f   = ch mh + cl mh + ch ml
// ============================================================================

__device__ float g_phi[1024];
__device__ float g_R[1024];
__device__ __nv_bfloat16 g_qs[16][64][128];  // [chunk][b][ qh(64) | ql(64) ]
__device__ __nv_bfloat16 g_ms[16][64][128];  // [chunk][b][ mh(64) | ml(64) ]

// ---------------- prep ----------------
__global__ void ssgp_prep_phi(const float* __restrict__ w) {
    int b = blockIdx.x * blockDim.x + threadIdx.x;   // 1024
    float S = w[b] + w[b + 1024];
    float C = w[2048 + b] - w[3072 + b];
    g_R[b] = sqrtf(S * S + C * C);
    g_phi[b] = atan2f(S, C);
}

__global__ void ssgp_prep_tab(const float* __restrict__ eps,
                              const float* __restrict__ lam,
                              const float* __restrict__ eta) {
    int idx = blockIdx.x * blockDim.x + threadIdx.x;  // 65536
    int b = idx >> 6, j = idx & 63;
    int ch = b >> 6, bp = b & 63;
    float e2 = eta[0] * eta[0];
    float q = eps[b * 64 + j] / lam[j];
    __nv_bfloat16 qh = __float2bfloat16_rn(q);
    __nv_bfloat16 ql = __float2bfloat16_rn(q - __bfloat162float(qh));
    g_qs[ch][bp][j]      = qh;
    g_qs[ch][bp][64 + j] = ql;

    float R = g_R[b];
    float m;
    if (j < 32) m = R * (eps[b * 64 + j + 32] / lam[j + 32]);
    else        m = -R * (eps[b * 64 + j - 32] / lam[j - 32] + e2 * q);
    __nv_bfloat16 mh = __float2bfloat16_rn(m);
    __nv_bfloat16 ml = __float2bfloat16_rn(m - __bfloat162float(mh));
    g_ms[ch][bp][j]      = mh;
    g_ms[ch][bp][64 + j] = ml;
}

// ---------------- asm helpers ----------------
__device__ __forceinline__ uint32_t smem_u32(const void* p) {
    uint32_t a;
    asm("{ .reg .u64 t; cvta.to.shared.u64 t, %1; cvt.u32.u64 %0, t; }" : "=r"(a) : "l"(p));
    return a;
}
__device__ __forceinline__ void mma16816(float* d, const uint32_t* a, const uint32_t* b) {
    asm volatile(
        "mma.sync.aligned.m16n8k16.row.col.f32.bf16.bf16.f32 "
        "{%0,%1,%2,%3}, {%4,%5,%6,%7}, {%8,%9}, {%0,%1,%2,%3};"
        : "+f"(d[0]), "+f"(d[1]), "+f"(d[2]), "+f"(d[3])
        : "r"(a[0]), "r"(a[1]), "r"(a[2]), "r"(a[3]), "r"(b[0]), "r"(b[1]));
}
__device__ __forceinline__ void ldsm_x4(uint32_t* r, uint32_t addr) {
    asm volatile("ldmatrix.sync.aligned.m8n8.x4.shared.b16 {%0,%1,%2,%3}, [%4];"
                 : "=r"(r[0]), "=r"(r[1]), "=r"(r[2]), "=r"(r[3]) : "r"(addr));
}
__device__ __forceinline__ void ldsm_x2(uint32_t* r, uint32_t addr) {
    asm volatile("ldmatrix.sync.aligned.m8n8.x2.shared.b16 {%0,%1}, [%2];"
                 : "=r"(r[0]), "=r"(r[1]) : "r"(addr));
}
__device__ __forceinline__ void ldsm_x2t(uint32_t* r, uint32_t addr) {
    asm volatile("ldmatrix.sync.aligned.m8n8.x2.trans.shared.b16 {%0,%1}, [%2];"
                 : "=r"(r[0]), "=r"(r[1]) : "r"(addr));
}
__device__ __forceinline__ void cpa16(uint32_t s, const void* g) {
    asm volatile("cp.async.cg.shared.global [%0], [%1], 16;" :: "r"(s), "l"(g));
}
__device__ __forceinline__ uint32_t pack_bf2(float lo, float hi) {
    __nv_bfloat162 v(__float2bfloat16_rn(lo), __float2bfloat16_rn(hi));
    return *(uint32_t*)&v;
}

// ---------------- smem layout ----------------
#define ROWB 272                  // 128 bf16 + 16B pad
#define SX_OFF 0                  // x tile: 64 rows x ROWB
#define Q_OFF  17408              // 4 bufs (half, dbuf)
#define M_OFF  (17408 + 4*17408)  // 87040, 4 bufs
#define PHI_OFF (87040 + 4*17408) // 156672, 1024 f32
#define SMEM_BYTES (156672 + 4096)
#define QBUF(h,d) (Q_OFF + ((h)*2+(d))*17408)
#define MBUF(h,d) (M_OFF + ((h)*2+(d))*17408)

__device__ __forceinline__ void pf_chunk(uint32_t sb, int half, int gc, int d, int t128) {
    uint32_t qdst = sb + QBUF(half, d);
    uint32_t mdst = sb + MBUF(half, d);
    const char* qsrc = (const char*)g_qs[gc];
    const char* msrc = (const char*)g_ms[gc];
#pragma unroll
    for (int r = 0; r < 8; r++) {
        int e = t128 + r * 128;                 // 1024 x 16B units
        uint32_t off = (uint32_t)(e >> 4) * ROWB + (uint32_t)(e & 15) * 16;
        cpa16(qdst + off, qsrc + e * 16);
        cpa16(mdst + off, msrc + e * 16);
    }
}

// ---------------- main ----------------
__global__ void __launch_bounds__(256, 1)
ssgp_hmma(const float* __restrict__ x, float* __restrict__ out) {
    extern __shared__ char smem[];
    const uint32_t sb = smem_u32(smem);
    const int tid = threadIdx.x, lane = tid & 31, w = tid >> 5;
    const int half = w >> 2, mrow = (w & 3) * 16;
    const int t128 = tid & 127;
    const int row0 = blockIdx.x * 64;
    const int c0 = half * 8;

    // prefetch phi + first two chunks for this half
    if (tid < 256) cpa16(sb + PHI_OFF + tid * 16, (const char*)g_phi + tid * 16);
    pf_chunk(sb, half, c0 + 0, 0, t128);
    asm volatile("cp.async.commit_group;");
    pf_chunk(sb, half, c0 + 1, 1, t128);
    asm volatile("cp.async.commit_group;");

    // stage x tile: 64 rows x [xh(64)|xl(64)] bf16, row stride ROWB
#pragma unroll
    for (int k = 0; k < 4; k++) {
        int e = tid + k * 256;                 // 1024 float4s
        int row = e >> 4, c4 = e & 15;
        float4 v = *(const float4*)&x[(row0 + row) * 64 + c4 * 4];
        float vh[4] = {v.x, v.y, v.z, v.w};
        uint32_t hp[2], lp[2];
#pragma unroll
        for (int p = 0; p < 2; p++) {
            float a = vh[2 * p], b = vh[2 * p + 1];
            float ah = __bfloat162float(__float2bfloat16_rn(a));
            float bh = __bfloat162float(__float2bfloat16_rn(b));
            hp[p] = pack_bf2(a, b);
            lp[p] = pack_bf2(a - ah, b - bh);
        }
        char* rp = smem + SX_OFF + row * ROWB;
        *(uint2*)(rp + c4 * 8)       = make_uint2(hp[0], hp[1]);
        *(uint2*)(rp + 128 + c4 * 8) = make_uint2(lp[0], lp[1]);
    }
    __syncthreads();

    // load persistent x A-fragments: [hi/lo][jb][4]
    uint32_t xa[2][4][4];
#pragma unroll
    for (int s = 0; s < 2; s++)
#pragma unroll
        for (int jb = 0; jb < 4; jb++) {
            uint32_t addr = sb + SX_OFF + (uint32_t)(mrow + (lane & 15)) * ROWB
                          + (uint32_t)(s * 64 + jb * 16 + ((lane >> 4) & 1) * 8) * 2;
            ldsm_x4(xa[s][jb], addr);
        }

    float f[8][4];
#pragma unroll
    for (int it = 0; it < 8; it++)
#pragma unroll
        for (int r = 0; r < 4; r++) f[it][r] = 0.f;

    const float* sphi = (const float*)(smem + PHI_OFF);

    for (int cc = 0; cc < 8; ++cc) {
        asm volatile("cp.async.wait_group 1;" ::: "memory");
        asm volatile("bar.sync %0, 128;" :: "r"(1 + half) : "memory");
        const uint32_t qb = sb + QBUF(half, cc & 1);
        const uint32_t mb = sb + MBUF(half, cc & 1);
        const int gc = c0 + cc;

        // ---- GEMM1: sim[16 x 64] = x . q^T over K=192 split ----
        float s[8][4];
#pragma unroll
        for (int nt = 0; nt < 8; nt++) {
#pragma unroll
            for (int r = 0; r < 4; r++) s[nt][r] = 0.f;
            uint32_t brow = qb + (uint32_t)(nt * 8 + (lane & 7)) * ROWB
                          + (uint32_t)(((lane >> 3) & 1) * 8) * 2;
            uint32_t bh[4][2], bl[4][2];
#pragma unroll
            for (int jb = 0; jb < 4; jb++) {
                ldsm_x2(bh[jb], brow + (uint32_t)(jb * 16) * 2);
                ldsm_x2(bl[jb], brow + (uint32_t)(64 + jb * 16) * 2);
            }
#pragma unroll
            for (int jb = 0; jb < 4; jb++) mma16816(s[nt], xa[0][jb], bh[jb]);
#pragma unroll
            for (int jb = 0; jb < 4; jb++) mma16816(s[nt], xa[1][jb], bh[jb]);
#pragma unroll
            for (int jb = 0; jb < 4; jb++) mma16816(s[nt], xa[0][jb], bl[jb]);
        }

        // ---- epilogue: cos(sim+phi) -> bf16 split -> A2 frags ----
        uint32_t ah[4][4], al[4][4];
#pragma unroll
        for (int nt = 0; nt < 8; nt++) {
            int cb = nt * 8 + (lane & 3) * 2;
            float p0 = sphi[gc * 64 + cb], p1 = sphi[gc * 64 + cb + 1];
            float v0 = __cosf(s[nt][0] + p0);
            float v1 = __cosf(s[nt][1] + p1);
            float v2 = __cosf(s[nt][2] + p0);
            float v3 = __cosf(s[nt][3] + p1);
            float h0 = __bfloat162float(__float2bfloat16_rn(v0));
            float h1 = __bfloat162float(__float2bfloat16_rn(v1));
            float h2 = __bfloat162float(__float2bfloat16_rn(v2));
            float h3 = __bfloat162float(__float2bfloat16_rn(v3));
            int t = nt >> 1, o = (nt & 1) * 2;
            ah[t][o]     = pack_bf2(v0, v1);
            ah[t][o + 1] = pack_bf2(v2, v3);
            al[t][o]     = pack_bf2(v0 - h0, v1 - h1);
            al[t][o + 1] = pack_bf2(v2 - h2, v3 - h3);
        }

        // ---- GEMM2: f += coeff . mat over K=64, split ----
#pragma unroll
        for (int it = 0; it < 8; it++) {
            uint32_t bcol = mb + (uint32_t)(lane & 15) * ROWB + (uint32_t)(it * 8) * 2;
            uint32_t bh[4][2], bl[4][2];
#pragma unroll
            for (int kb = 0; kb < 4; kb++) {
                ldsm_x2t(bh[kb], bcol + (uint32_t)(kb * 16) * ROWB);
                ldsm_x2t(bl[kb], bcol + (uint32_t)(kb * 16) * ROWB + 128);
            }
#pragma unroll
            for (int kb = 0; kb < 4; kb++) mma16816(f[it], ah[kb], bh[kb]);
#pragma unroll
            for (int kb = 0; kb < 4; kb++) mma16816(f[it], al[kb], bh[kb]);
#pragma unroll
            for (int kb = 0; kb < 4; kb++) mma16816(f[it], ah[kb], bl[kb]);
        }

        asm volatile("bar.sync %0, 128;" :: "r"(1 + half) : "memory");
        if (cc + 2 < 8) pf_chunk(sb, half, c0 + cc + 2, cc & 1, t128);
        asm volatile("cp.async.commit_group;");
    }

    // ---- write per-half partials to smem (reuse q bufs), combine ----
    float* sf = (float*)(smem + QBUF(half, 0));   // 64 x 68 f32 = 17408B
    {
        int r = mrow + lane / 4;
        int cbase = (lane & 3) * 2;
#pragma unroll
        for (int it = 0; it < 8; it++) {
            int col = it * 8 + cbase;
            *(float2*)&sf[r * 68 + col]       = make_float2(f[it][0], f[it][1]);
            *(float2*)&sf[(r + 8) * 68 + col] = make_float2(f[it][2], f[it][3]);
        }
    }
    __syncthreads();
    const float* sf0 = (const float*)(smem + QBUF(0, 0));
    const float* sf1 = (const float*)(smem + QBUF(1, 0));
#pragma unroll
    for (int k = 0; k < 4; k++) {
        int e = tid + k * 256;
        int row = e >> 4, c4 = (e & 15) * 4;
        float4 a = *(const float4*)&sf0[row * 68 + c4];
        float4 b = *(const float4*)&sf1[row * 68 + c4];
        float4 o;
        o.x = a.x + b.x; o.y = a.y + b.y; o.z = a.z + b.z; o.w = a.w + b.w;
        *(float4*)&out[(row0 + row) * 64 + c4] = o;
    }
}

extern "C" void kernel_launch(void* const* d_in, const int* in_sizes, int n_in,
                              void* d_out, int out_size) {
    // inputs: 0=t(1), 1=x(8192*64), 2=epsilon(2048*64), 3=lam(64), 4=eta(1), 5=w(4096)
    const float* x   = (const float*)d_in[1];
    const float* eps = (const float*)d_in[2];
    const float* lam = (const float*)d_in[3];
    const float* eta = (const float*)d_in[4];
    const float* w   = (const float*)d_in[5];
    float* out = (float*)d_out;

    ssgp_prep_phi<<<4, 256>>>(w);
    ssgp_prep_tab<<<256, 256>>>(eps, lam, eta);

    cudaFuncSetAttribute(ssgp_hmma, cudaFuncAttributeMaxDynamicSharedMemorySize,
                         SMEM_BYTES);
    ssgp_hmma<<<128, 256, SMEM_BYTES>>>(x, out);
}